// round 9
// baseline (speedup 1.0000x reference)
#include <cuda_runtime.h>
#include <math.h>

#define Bq 512
#define Sq 4096
#define Dq 128
#define Vq 6
#define Kq 409

// Precomputed per-token-value tables
__device__ float g_score[Vq];
__device__ float g_att[Vq * Dq];

// ---------------------------------------------------------------------------
// Kernel 1: precompute — 6 blocks (one per token value) x 256 threads.
// ---------------------------------------------------------------------------
__global__ __launch_bounds__(256) void precompute_kernel(
    const float* __restrict__ emb,
    const float* __restrict__ W1, const float* __restrict__ b1,
    const float* __restrict__ W2, const float* __restrict__ b2,
    const float* __restrict__ W3, const float* __restrict__ b3,
    const float* __restrict__ A1, const float* __restrict__ a1,
    const float* __restrict__ A2, const float* __restrict__ a2)
{
    const int v = blockIdx.x;
    const int t = threadIdx.x;  // 256 threads
    __shared__ float e[Dq];
    __shared__ float h1[64];
    __shared__ float g1[64];
    __shared__ float h2[32];

    if (t < Dq) e[t] = emb[v * Dq + t];
    __syncthreads();

    // layer 1: both W1 and A1. 256 threads = 2 mats x 64 neurons x 2 halves.
    {
        const int mat = t >> 7;          // 0 -> W1 path, 1 -> A1 path
        const int n   = (t & 127) >> 1;  // neuron 0..63
        const int p   = t & 1;           // half 0..1
        const float* M = mat ? A1 : W1;
        float s = 0.f;
        const int base = p * 64;
        #pragma unroll
        for (int i = 0; i < 64; i++)
            s += e[base + i] * M[(base + i) * 64 + n];
        s += __shfl_xor_sync(0xffffffff, s, 1);
        if (p == 0) {
            if (mat == 0) h1[n] = fmaxf(s + b1[n], 0.f);
            else          g1[n] = fmaxf(s + a1[n], 0.f);
        }
    }
    __syncthreads();

    // layer 2 (W2): 32 neurons x 4 threads (uses threads 0..127)
    if (t < 128) {
        const int n = t >> 2, p = t & 3;
        float s = 0.f;
        const int base = p * 16;
        #pragma unroll
        for (int i = 0; i < 16; i++)
            s += h1[base + i] * W2[(base + i) * 32 + n];
        s += __shfl_xor_sync(0xffffffff, s, 1);
        s += __shfl_xor_sync(0xffffffff, s, 2);
        if (p == 0) h2[n] = fmaxf(s + b2[n], 0.f);
    }
    // A2: 128 outputs x 2 threads (all 256 threads)
    {
        const int j = t >> 1, p = t & 1;
        float s = 0.f;
        const int base = p * 32;
        #pragma unroll
        for (int i = 0; i < 32; i++)
            s += g1[base + i] * A2[(base + i) * Dq + j];
        s += __shfl_xor_sync(0xffffffff, s, 1);
        if (p == 0) g_att[v * Dq + j] = s + a2[j];
    }
    __syncthreads();

    // layer 3: warp 0 reduces 32 values -> sigmoid score
    if (t < 32) {
        float z = h2[t] * W3[t];
        #pragma unroll
        for (int d = 16; d >= 1; d >>= 1) z += __shfl_xor_sync(0xffffffff, z, d);
        if (t == 0) g_score[v] = 1.f / (1.f + expf(-(z + b3[0])));
    }
}

// ---------------------------------------------------------------------------
// Kernel 2: one CTA per batch row. 256 threads, 16 contiguous tokens/thread.
// Single 10-bit-packed u64 warp scan; redundant per-thread take/off calc;
// 3 block barriers total. launch_bounds caps regs for single-wave residency.
// ---------------------------------------------------------------------------
__global__ __launch_bounds__(256, 4) void main_kernel(
    const int* __restrict__ x,
    const float* __restrict__ C1, const float* __restrict__ c1,
    const float* __restrict__ C2, const float* __restrict__ c2,
    float* __restrict__ out)
{
    const int b = blockIdx.x;
    const int t = threadIdx.x;  // 256 threads
    const int w = t >> 5, l = t & 31;

    __shared__ unsigned long long wtot[8];  // per-warp packed totals
    __shared__ float sh_idx[Kq];
    __shared__ float pooled[Dq];
    __shared__ float hcls[64];

    const float s0 = g_score[0], s1 = g_score[1], s2 = g_score[2];
    const float s3 = g_score[3], s4 = g_score[4], s5 = g_score[5];

    const int4* xb = (const int4*)(x + (size_t)b * Sq);
    float* fs = out + Bq + (size_t)Bq * Kq + (size_t)b * Sq;

    // thread t owns tokens [16t, 16t+16)
    int4 P[4];
    unsigned long long hist = 0ull;
    #pragma unroll
    for (int i = 0; i < 4; i++) {
        int4 p = xb[t * 4 + i];
        P[i] = p;
        float4 f;
        float* fp = (float*)&f;
        const int* pv = (const int*)&p;
        #pragma unroll
        for (int j = 0; j < 4; j++) {
            const int v = pv[j];
            float sc = s0;
            sc = (v == 1) ? s1 : sc;
            sc = (v == 2) ? s2 : sc;
            sc = (v == 3) ? s3 : sc;
            sc = (v == 4) ? s4 : sc;
            sc = (v == 5) ? s5 : sc;
            fp[j] = sc;
            hist += 1ull << (v * 10);   // 10-bit fields: <=512/warp, no overflow
        }
        ((float4*)fs)[t * 4 + i] = f;
    }

    // warp-level packed inclusive scan
    unsigned long long run = hist;
    #pragma unroll
    for (int d = 1; d < 32; d <<= 1) {
        unsigned long long o = __shfl_up_sync(0xffffffff, run, d);
        if (l >= d) run += o;
    }
    const unsigned long long excl = run - hist;
    if (l == 31) wtot[w] = run;
    __syncthreads();  // barrier 1

    // every thread: cross-warp bases + totals + order + take/off (redundant)
    int base[Vq], tot[Vq];
    {
        unsigned long long pre = 0ull, all = 0ull;
        #pragma unroll
        for (int ww = 0; ww < 8; ww++) {
            unsigned long long tw = wtot[ww];
            if (ww < w) pre += tw;
            all += tw;
        }
        pre += excl;
        #pragma unroll
        for (int v = 0; v < Vq; v++) {
            base[v] = (int)((pre >> (v * 10)) & 0x3FF);
            tot[v]  = (int)((all >> (v * 10)) & 0x3FF);
        }
    }
    int take[Vq], off[Vq];
    {
        float sc[Vq] = {s0, s1, s2, s3, s4, s5};
        bool used[Vq];
        #pragma unroll
        for (int v = 0; v < Vq; v++) used[v] = false;
        int rem = Kq, o = 0;
        #pragma unroll
        for (int g = 0; g < Vq; g++) {
            int best = 0; float bs = -1e30f;
            #pragma unroll
            for (int v = 0; v < Vq; v++)
                if (!used[v] && sc[v] > bs) { bs = sc[v]; best = v; }
            used[best] = true;
            int tk = min(tot[best], rem);
            take[best] = tk; off[best] = o;
            o += tk; rem -= tk;
        }
    }

    // pooled (issue g_att global loads early; overlap with compaction below)
    float pooled_val = 0.f;
    if (t < Dq) {
        #pragma unroll
        for (int v = 0; v < Vq; v++)
            pooled_val += (float)take[v] * g_att[v * Dq + t];
        pooled[t] = pooled_val * (1.f / (float)Kq);
    }

    // compaction into shared
    #pragma unroll
    for (int i = 0; i < 4; i++) {
        const int* pv = (const int*)&P[i];
        #pragma unroll
        for (int j = 0; j < 4; j++) {
            const int vv = pv[j];
            int rank = 0, tk = 0, of = 0;
            #pragma unroll
            for (int v = 0; v < Vq; v++)
                if (vv == v) { rank = base[v]++; tk = take[v]; of = off[v]; }
            if (rank < tk) sh_idx[of + rank] = (float)(t * 16 + i * 4 + j);
        }
    }
    __syncthreads();  // barrier 2

    float* oidx = out + Bq + (size_t)b * Kq;
    oidx[t] = sh_idx[t];
    if (t < Kq - 256) oidx[t + 256] = sh_idx[t + 256];

    // classifier layer 1: 64 neurons x 4 threads (32 inputs each)
    {
        const int n = t >> 2, q = t & 3;
        float s = 0.f;
        const int bse = q * 32;
        #pragma unroll 8
        for (int i = 0; i < 32; i++)
            s += pooled[bse + i] * C1[(bse + i) * 64 + n];
        s += __shfl_xor_sync(0xffffffff, s, 1);
        s += __shfl_xor_sync(0xffffffff, s, 2);
        if (q == 0) hcls[n] = fmaxf(s + c1[n], 0.f);
    }
    __syncthreads();  // barrier 3

    // classifier layer 2: one warp reduces 64 values
    if (t < 32) {
        float z = hcls[t] * C2[t] + hcls[t + 32] * C2[t + 32];
        #pragma unroll
        for (int d = 16; d >= 1; d >>= 1) z += __shfl_xor_sync(0xffffffff, z, d);
        if (t == 0) out[b] = 1.f / (1.f + expf(-(z + c2[0])));
    }
}

extern "C" void kernel_launch(void* const* d_in, const int* in_sizes, int n_in,
                              void* d_out, int out_size) {
    const int*   x   = (const int*)d_in[0];
    const float* emb = (const float*)d_in[1];
    const float* W1  = (const float*)d_in[2];
    const float* b1  = (const float*)d_in[3];
    const float* W2  = (const float*)d_in[4];
    const float* b2  = (const float*)d_in[5];
    const float* W3  = (const float*)d_in[6];
    const float* b3  = (const float*)d_in[7];
    const float* A1  = (const float*)d_in[8];
    const float* a1  = (const float*)d_in[9];
    const float* A2  = (const float*)d_in[10];
    const float* a2  = (const float*)d_in[11];
    const float* C1  = (const float*)d_in[12];
    const float* c1  = (const float*)d_in[13];
    const float* C2  = (const float*)d_in[14];
    const float* c2  = (const float*)d_in[15];
    float* out = (float*)d_out;

    precompute_kernel<<<Vq, 256>>>(emb, W1, b1, W2, b2, W3, b3, A1, a1, A2, a2);
    main_kernel<<<Bq, 256>>>(x, C1, c1, C2, c2, out);
}

// round 11
// speedup vs baseline: 1.2931x; 1.2931x over previous
#include <cuda_runtime.h>
#include <math.h>

#define Bq 512
#define Sq 4096
#define Dq 128
#define Vq 6
#define Kq 409

// Precomputed per-token-value tables
__device__ float g_score[Vq];
__device__ float g_att[Vq * Dq];

// ---------------------------------------------------------------------------
// Kernel 1: precompute — 6 blocks (one per token value) x 256 threads.
// Triggers programmatic launch completion at entry so main_kernel's
// score-independent front half overlaps with this kernel.
// ---------------------------------------------------------------------------
__global__ __launch_bounds__(256) void precompute_kernel(
    const float* __restrict__ emb,
    const float* __restrict__ W1, const float* __restrict__ b1,
    const float* __restrict__ W2, const float* __restrict__ b2,
    const float* __restrict__ W3, const float* __restrict__ b3,
    const float* __restrict__ A1, const float* __restrict__ a1,
    const float* __restrict__ A2, const float* __restrict__ a2)
{
#if __CUDA_ARCH__ >= 900
    cudaTriggerProgrammaticLaunchCompletion();
#endif
    const int v = blockIdx.x;
    const int t = threadIdx.x;  // 256 threads
    __shared__ float e[Dq];
    __shared__ float h1[64];
    __shared__ float g1[64];
    __shared__ float h2[32];

    if (t < Dq) e[t] = emb[v * Dq + t];
    __syncthreads();

    // layer 1: both W1 and A1. 256 threads = 2 mats x 64 neurons x 2 halves.
    {
        const int mat = t >> 7;          // 0 -> W1 path, 1 -> A1 path
        const int n   = (t & 127) >> 1;  // neuron 0..63
        const int p   = t & 1;           // half 0..1
        const float* M = mat ? A1 : W1;
        float s = 0.f;
        const int base = p * 64;
        #pragma unroll
        for (int i = 0; i < 64; i++)
            s += e[base + i] * M[(base + i) * 64 + n];
        s += __shfl_xor_sync(0xffffffff, s, 1);
        if (p == 0) {
            if (mat == 0) h1[n] = fmaxf(s + b1[n], 0.f);
            else          g1[n] = fmaxf(s + a1[n], 0.f);
        }
    }
    __syncthreads();

    // layer 2 (W2): 32 neurons x 4 threads (uses threads 0..127)
    if (t < 128) {
        const int n = t >> 2, p = t & 3;
        float s = 0.f;
        const int base = p * 16;
        #pragma unroll
        for (int i = 0; i < 16; i++)
            s += h1[base + i] * W2[(base + i) * 32 + n];
        s += __shfl_xor_sync(0xffffffff, s, 1);
        s += __shfl_xor_sync(0xffffffff, s, 2);
        if (p == 0) h2[n] = fmaxf(s + b2[n], 0.f);
    }
    // A2: 128 outputs x 2 threads (all 256 threads)
    {
        const int j = t >> 1, p = t & 1;
        float s = 0.f;
        const int base = p * 32;
        #pragma unroll
        for (int i = 0; i < 32; i++)
            s += g1[base + i] * A2[(base + i) * Dq + j];
        s += __shfl_xor_sync(0xffffffff, s, 1);
        if (p == 0) g_att[v * Dq + j] = s + a2[j];
    }
    __syncthreads();

    // layer 3: warp 0 reduces 32 values -> sigmoid score
    if (t < 32) {
        float z = h2[t] * W3[t];
        #pragma unroll
        for (int d = 16; d >= 1; d >>= 1) z += __shfl_xor_sync(0xffffffff, z, d);
        if (t == 0) g_score[v] = 1.f / (1.f + expf(-(z + b3[0])));
    }
}

// ---------------------------------------------------------------------------
// Kernel 2: one CTA per batch row. 256 threads, 16 contiguous tokens/thread.
// Score-independent front half (loads, histogram, scan) runs BEFORE the
// grid-dependency sync -> overlaps with precompute via PDL.
// ---------------------------------------------------------------------------
__global__ __launch_bounds__(256, 4) void main_kernel(
    const int* __restrict__ x,
    const float* __restrict__ C1, const float* __restrict__ c1,
    const float* __restrict__ C2, const float* __restrict__ c2,
    float* __restrict__ out)
{
    const int b = blockIdx.x;
    const int t = threadIdx.x;  // 256 threads
    const int w = t >> 5, l = t & 31;

    __shared__ unsigned long long wtot[8];  // per-warp packed totals
    __shared__ float sh_idx[Kq];
    __shared__ float pooled[Dq];
    __shared__ float hcls[64];

    // ---------- score-independent front half ----------
    const int4* xb = (const int4*)(x + (size_t)b * Sq);

    int4 P[4];
    unsigned long long hist = 0ull;
    #pragma unroll
    for (int i = 0; i < 4; i++) {
        int4 p = xb[t * 4 + i];
        P[i] = p;
        hist += 1ull << (p.x * 10);
        hist += 1ull << (p.y * 10);
        hist += 1ull << (p.z * 10);
        hist += 1ull << (p.w * 10);
    }

    // warp-level packed inclusive scan (10-bit fields, <=512/warp)
    unsigned long long run = hist;
    #pragma unroll
    for (int d = 1; d < 32; d <<= 1) {
        unsigned long long o = __shfl_up_sync(0xffffffff, run, d);
        if (l >= d) run += o;
    }
    const unsigned long long excl = run - hist;
    if (l == 31) wtot[w] = run;
    __syncthreads();  // barrier 1

    int base[Vq], tot[Vq];
    {
        unsigned long long pre = 0ull, all = 0ull;
        #pragma unroll
        for (int ww = 0; ww < 8; ww++) {
            unsigned long long tw = wtot[ww];
            if (ww < w) pre += tw;
            all += tw;
        }
        pre += excl;
        #pragma unroll
        for (int v = 0; v < Vq; v++) {
            base[v] = (int)((pre >> (v * 10)) & 0x3FF);
            tot[v]  = (int)((all >> (v * 10)) & 0x3FF);
        }
    }

    // ---------- wait for precompute results ----------
#if __CUDA_ARCH__ >= 900
    cudaGridDependencySynchronize();
#endif

    float sc[Vq];
    #pragma unroll
    for (int v = 0; v < Vq; v++) sc[v] = g_score[v];

    // final_scores writes (SEL chain off score regs)
    float* fs = out + Bq + (size_t)Bq * Kq + (size_t)b * Sq;
    #pragma unroll
    for (int i = 0; i < 4; i++) {
        float4 f;
        float* fp = (float*)&f;
        const int* pv = (const int*)&P[i];
        #pragma unroll
        for (int j = 0; j < 4; j++) {
            const int v = pv[j];
            float s = sc[0];
            s = (v == 1) ? sc[1] : s;
            s = (v == 2) ? sc[2] : s;
            s = (v == 3) ? sc[3] : s;
            s = (v == 4) ? sc[4] : s;
            s = (v == 5) ? sc[5] : s;
            fp[j] = s;
        }
        ((float4*)fs)[t * 4 + i] = f;
    }

    // branchless rank-based take/off:
    //   u precedes v  <=>  s_u > s_v  ||  (s_u == s_v && u < v)
    int take[Vq], off[Vq];
    #pragma unroll
    for (int v = 0; v < Vq; v++) {
        int offraw = 0;
        #pragma unroll
        for (int u = 0; u < Vq; u++) {
            if (u == v) continue;
            bool prec = (sc[u] > sc[v]) || (sc[u] == sc[v] && u < v);
            offraw += prec ? tot[u] : 0;
        }
        off[v]  = min(offraw, Kq);
        take[v] = max(0, min(Kq - offraw, tot[v]));
    }

    // pooled: issue g_att loads now (overlap with compaction ALU)
    if (t < Dq) {
        float s = 0.f;
        #pragma unroll
        for (int v = 0; v < Vq; v++)
            s += (float)take[v] * g_att[v * Dq + t];
        pooled[t] = s * (1.f / (float)Kq);
    }

    // compaction into shared
    #pragma unroll
    for (int i = 0; i < 4; i++) {
        const int* pv = (const int*)&P[i];
        #pragma unroll
        for (int j = 0; j < 4; j++) {
            const int vv = pv[j];
            int rank = 0, tk = 0, of = 0;
            #pragma unroll
            for (int v = 0; v < Vq; v++)
                if (vv == v) { rank = base[v]++; tk = take[v]; of = off[v]; }
            if (rank < tk) sh_idx[of + rank] = (float)(t * 16 + i * 4 + j);
        }
    }
    __syncthreads();  // barrier 2

    float* oidx = out + Bq + (size_t)b * Kq;
    oidx[t] = sh_idx[t];
    if (t < Kq - 256) oidx[t + 256] = sh_idx[t + 256];

    // classifier layer 1: 64 neurons x 4 threads (32 inputs each)
    {
        const int n = t >> 2, q = t & 3;
        float s = 0.f;
        const int bse = q * 32;
        #pragma unroll 8
        for (int i = 0; i < 32; i++)
            s += pooled[bse + i] * C1[(bse + i) * 64 + n];
        s += __shfl_xor_sync(0xffffffff, s, 1);
        s += __shfl_xor_sync(0xffffffff, s, 2);
        if (q == 0) hcls[n] = fmaxf(s + c1[n], 0.f);
    }
    __syncthreads();  // barrier 3

    // classifier layer 2: one warp reduces 64 values
    if (t < 32) {
        float z = hcls[t] * C2[t] + hcls[t + 32] * C2[t + 32];
        #pragma unroll
        for (int d = 16; d >= 1; d >>= 1) z += __shfl_xor_sync(0xffffffff, z, d);
        if (t == 0) out[b] = 1.f / (1.f + expf(-(z + c2[0])));
    }
}

extern "C" void kernel_launch(void* const* d_in, const int* in_sizes, int n_in,
                              void* d_out, int out_size) {
    const int*   x   = (const int*)d_in[0];
    const float* emb = (const float*)d_in[1];
    const float* W1  = (const float*)d_in[2];
    const float* b1  = (const float*)d_in[3];
    const float* W2  = (const float*)d_in[4];
    const float* b2  = (const float*)d_in[5];
    const float* W3  = (const float*)d_in[6];
    const float* b3  = (const float*)d_in[7];
    const float* A1  = (const float*)d_in[8];
    const float* a1  = (const float*)d_in[9];
    const float* A2  = (const float*)d_in[10];
    const float* a2  = (const float*)d_in[11];
    const float* C1  = (const float*)d_in[12];
    const float* c1  = (const float*)d_in[13];
    const float* C2  = (const float*)d_in[14];
    const float* c2  = (const float*)d_in[15];
    float* out = (float*)d_out;

    precompute_kernel<<<Vq, 256>>>(emb, W1, b1, W2, b2, W3, b3, A1, a1, A2, a2);

    // Secondary launch with programmatic stream serialization (PDL):
    // main_kernel may begin before precompute finishes; it gates on
    // cudaGridDependencySynchronize() before consuming g_score/g_att.
    cudaLaunchConfig_t cfg = {};
    cfg.gridDim  = dim3(Bq, 1, 1);
    cfg.blockDim = dim3(256, 1, 1);
    cfg.dynamicSmemBytes = 0;
    cfg.stream = 0;
    cudaLaunchAttribute attr[1];
    attr[0].id = cudaLaunchAttributeProgrammaticStreamSerialization;
    attr[0].val.programmaticStreamSerializationAllowed = 1;
    cfg.attrs = attr;
    cfg.numAttrs = 1;
    cudaLaunchKernelEx(&cfg, main_kernel, x, C1, c1, C2, c2, out);
}

// round 12
// speedup vs baseline: 1.4307x; 1.1064x over previous
#include <cuda_runtime.h>
#include <math.h>

#define Bq 512
#define Sq 4096
#define Dq 128
#define Vq 6
#define Kq 409

// Precomputed per-token-value tables
__device__ float g_score[Vq];
__device__ float g_att[Vq * Dq];

// ---------------------------------------------------------------------------
// Kernel 1: precompute — 6 blocks (one per token value) x 256 threads.
// Triggers programmatic launch completion at entry so main_kernel's
// score-independent front half overlaps with this kernel.
// ---------------------------------------------------------------------------
__global__ __launch_bounds__(256) void precompute_kernel(
    const float* __restrict__ emb,
    const float* __restrict__ W1, const float* __restrict__ b1,
    const float* __restrict__ W2, const float* __restrict__ b2,
    const float* __restrict__ W3, const float* __restrict__ b3,
    const float* __restrict__ A1, const float* __restrict__ a1,
    const float* __restrict__ A2, const float* __restrict__ a2)
{
#if __CUDA_ARCH__ >= 900
    cudaTriggerProgrammaticLaunchCompletion();
#endif
    const int v = blockIdx.x;
    const int t = threadIdx.x;  // 256 threads
    __shared__ float e[Dq];
    __shared__ float h1[64];
    __shared__ float g1[64];
    __shared__ float h2[32];

    if (t < Dq) e[t] = emb[v * Dq + t];
    __syncthreads();

    // layer 1: both W1 and A1. 256 threads = 2 mats x 64 neurons x 2 halves.
    {
        const int mat = t >> 7;          // 0 -> W1 path, 1 -> A1 path
        const int n   = (t & 127) >> 1;  // neuron 0..63
        const int p   = t & 1;           // half 0..1
        const float* M = mat ? A1 : W1;
        float s = 0.f;
        const int base = p * 64;
        #pragma unroll
        for (int i = 0; i < 64; i++)
            s += e[base + i] * M[(base + i) * 64 + n];
        s += __shfl_xor_sync(0xffffffff, s, 1);
        if (p == 0) {
            if (mat == 0) h1[n] = fmaxf(s + b1[n], 0.f);
            else          g1[n] = fmaxf(s + a1[n], 0.f);
        }
    }
    __syncthreads();

    // layer 2 (W2): 32 neurons x 4 threads (uses threads 0..127)
    if (t < 128) {
        const int n = t >> 2, p = t & 3;
        float s = 0.f;
        const int base = p * 16;
        #pragma unroll
        for (int i = 0; i < 16; i++)
            s += h1[base + i] * W2[(base + i) * 32 + n];
        s += __shfl_xor_sync(0xffffffff, s, 1);
        s += __shfl_xor_sync(0xffffffff, s, 2);
        if (p == 0) h2[n] = fmaxf(s + b2[n], 0.f);
    }
    // A2: 128 outputs x 2 threads (all 256 threads)
    {
        const int j = t >> 1, p = t & 1;
        float s = 0.f;
        const int base = p * 32;
        #pragma unroll
        for (int i = 0; i < 32; i++)
            s += g1[base + i] * A2[(base + i) * Dq + j];
        s += __shfl_xor_sync(0xffffffff, s, 1);
        if (p == 0) g_att[v * Dq + j] = s + a2[j];
    }
    __syncthreads();

    // layer 3: warp 0 reduces 32 values -> sigmoid score
    if (t < 32) {
        float z = h2[t] * W3[t];
        #pragma unroll
        for (int d = 16; d >= 1; d >>= 1) z += __shfl_xor_sync(0xffffffff, z, d);
        if (t == 0) g_score[v] = 1.f / (1.f + expf(-(z + b3[0])));
    }
}

// ---------------------------------------------------------------------------
// Kernel 2: one CTA per batch row. 256 threads, 16 contiguous tokens/thread.
// Dynamic-index work routed through SHFL (score gather, offraw gather) and
// packed-u64 rank fields; the pos<K test absorbs both take/off clamps.
// ---------------------------------------------------------------------------
__global__ __launch_bounds__(256, 4) void main_kernel(
    const int* __restrict__ x,
    const float* __restrict__ C1, const float* __restrict__ c1,
    const float* __restrict__ C2, const float* __restrict__ c2,
    float* __restrict__ out)
{
    const int b = blockIdx.x;
    const int t = threadIdx.x;  // 256 threads
    const int w = t >> 5, l = t & 31;

    __shared__ unsigned long long wtot[8];  // per-warp packed totals
    __shared__ float sh_idx[Kq];
    __shared__ float pooled[Dq];
    __shared__ float hcls[64];

    // ---------- score-independent front half (overlaps precompute) ----------
    const int4* xb = (const int4*)(x + (size_t)b * Sq);

    int4 P[4];
    unsigned long long hist = 0ull;
    #pragma unroll
    for (int i = 0; i < 4; i++) {
        int4 p = xb[t * 4 + i];
        P[i] = p;
        hist += 1ull << (p.x * 10);
        hist += 1ull << (p.y * 10);
        hist += 1ull << (p.z * 10);
        hist += 1ull << (p.w * 10);
    }

    // warp-level packed inclusive scan (10-bit fields)
    unsigned long long run = hist;
    #pragma unroll
    for (int d = 1; d < 32; d <<= 1) {
        unsigned long long o = __shfl_up_sync(0xffffffff, run, d);
        if (l >= d) run += o;
    }
    const unsigned long long excl = run - hist;
    if (l == 31) wtot[w] = run;
    __syncthreads();  // barrier 1

    // cross-warp: packed exclusive base (pcnt) + per-value block totals
    unsigned long long pcnt;
    int tot[Vq];
    {
        unsigned long long pre = 0ull, all = 0ull;
        #pragma unroll
        for (int ww = 0; ww < 8; ww++) {
            unsigned long long tw = wtot[ww];
            if (ww < w) pre += tw;
            all += tw;
        }
        pcnt = pre + excl;   // packed per-value rank counters for this thread
        #pragma unroll
        for (int v = 0; v < Vq; v++)
            tot[v] = (int)((all >> (v * 10)) & 0x3FF);
    }

    // ---------- wait for precompute results ----------
#if __CUDA_ARCH__ >= 900
    cudaGridDependencySynchronize();
#endif

    float sc[Vq];
    #pragma unroll
    for (int v = 0; v < Vq; v++) sc[v] = g_score[v];

    // lane-resident score for dynamic gather via shfl
    const int v_me = (l < Vq) ? l : (Vq - 1);
    const float scf = sc[v_me];

    // per-lane rank offset: offraw_l = sum of tot[u] for u preceding v_me
    // (u precedes v  <=>  s_u > s_v || (s_u == s_v && u < v))
    int offraw_lane = 0;
    #pragma unroll
    for (int u = 0; u < Vq; u++) {
        bool prec = (u != v_me) &&
                    ((sc[u] > sc[v_me]) || (sc[u] == sc[v_me] && u < v_me));
        offraw_lane += prec ? tot[u] : 0;
    }

    // ---------- fused fs-store + compaction pass ----------
    float* fs = out + Bq + (size_t)Bq * Kq + (size_t)b * Sq;
    #pragma unroll
    for (int i = 0; i < 4; i++) {
        const int* pv = (const int*)&P[i];
        float4 f;
        float* fp = (float*)&f;
        #pragma unroll
        for (int j = 0; j < 4; j++) {
            const int vv = pv[j];
            fp[j] = __shfl_sync(0xffffffff, scf, vv);
            const int ofr = __shfl_sync(0xffffffff, offraw_lane, vv);
            const int sh = vv * 10;
            const int rank = (int)((pcnt >> sh) & 0x3FF);
            pcnt += 1ull << sh;
            const int pos = ofr + rank;
            if (pos < Kq) sh_idx[pos] = (float)(t * 16 + i * 4 + j);
        }
        ((float4*)fs)[t * 4 + i] = f;
    }

    // pooled: take[v] recovered via static-lane shfls of offraw
    if (t < Dq) {   // warps 0..3 fully active -> shfl safe
        float s = 0.f;
        #pragma unroll
        for (int v = 0; v < Vq; v++) {
            const int ofr = __shfl_sync(0xffffffff, offraw_lane, v);
            const int tk = max(0, min(Kq - ofr, tot[v]));
            s += (float)tk * g_att[v * Dq + t];
        }
        pooled[t] = s * (1.f / (float)Kq);
    }
    __syncthreads();  // barrier 2

    float* oidx = out + Bq + (size_t)b * Kq;
    oidx[t] = sh_idx[t];
    if (t < Kq - 256) oidx[t + 256] = sh_idx[t + 256];

    // classifier layer 1: 64 neurons x 4 threads (32 inputs each)
    {
        const int n = t >> 2, q = t & 3;
        float s = 0.f;
        const int bse = q * 32;
        #pragma unroll 8
        for (int i = 0; i < 32; i++)
            s += pooled[bse + i] * C1[(bse + i) * 64 + n];
        s += __shfl_xor_sync(0xffffffff, s, 1);
        s += __shfl_xor_sync(0xffffffff, s, 2);
        if (q == 0) hcls[n] = fmaxf(s + c1[n], 0.f);
    }
    __syncthreads();  // barrier 3

    // classifier layer 2: one warp reduces 64 values
    if (t < 32) {
        float z = hcls[t] * C2[t] + hcls[t + 32] * C2[t + 32];
        #pragma unroll
        for (int d = 16; d >= 1; d >>= 1) z += __shfl_xor_sync(0xffffffff, z, d);
        if (t == 0) out[b] = 1.f / (1.f + expf(-(z + c2[0])));
    }
}

extern "C" void kernel_launch(void* const* d_in, const int* in_sizes, int n_in,
                              void* d_out, int out_size) {
    const int*   x   = (const int*)d_in[0];
    const float* emb = (const float*)d_in[1];
    const float* W1  = (const float*)d_in[2];
    const float* b1  = (const float*)d_in[3];
    const float* W2  = (const float*)d_in[4];
    const float* b2  = (const float*)d_in[5];
    const float* W3  = (const float*)d_in[6];
    const float* b3  = (const float*)d_in[7];
    const float* A1  = (const float*)d_in[8];
    const float* a1  = (const float*)d_in[9];
    const float* A2  = (const float*)d_in[10];
    const float* a2  = (const float*)d_in[11];
    const float* C1  = (const float*)d_in[12];
    const float* c1  = (const float*)d_in[13];
    const float* C2  = (const float*)d_in[14];
    const float* c2  = (const float*)d_in[15];
    float* out = (float*)d_out;

    precompute_kernel<<<Vq, 256>>>(emb, W1, b1, W2, b2, W3, b3, A1, a1, A2, a2);

    // PDL: main_kernel may begin before precompute finishes; it gates on
    // cudaGridDependencySynchronize() before consuming g_score/g_att.
    cudaLaunchConfig_t cfg = {};
    cfg.gridDim  = dim3(Bq, 1, 1);
    cfg.blockDim = dim3(256, 1, 1);
    cfg.dynamicSmemBytes = 0;
    cfg.stream = 0;
    cudaLaunchAttribute attr[1];
    attr[0].id = cudaLaunchAttributeProgrammaticStreamSerialization;
    attr[0].val.programmaticStreamSerializationAllowed = 1;
    cfg.attrs = attr;
    cfg.numAttrs = 1;
    cudaLaunchKernelEx(&cfg, main_kernel, x, C1, c1, C2, c2, out);
}

// round 13
// speedup vs baseline: 1.7945x; 1.2542x over previous
#include <cuda_runtime.h>
#include <math.h>

#define Bq 512
#define Sq 4096
#define Dq 128
#define Vq 6
#define Kq 409

// Precomputed per-token-value tables
__device__ float g_score[Vq];
__device__ float g_attC1[Vq * 64];   // att_v @ C1  (classifier layer-1 fold)

// ---------------------------------------------------------------------------
// Kernel 1: precompute — 6 blocks (one per token value) x 256 threads.
// Computes score_v and the folded classifier table attC1[v] = att_v @ C1.
// Triggers PDL launch completion at entry.
// ---------------------------------------------------------------------------
__global__ __launch_bounds__(256) void precompute_kernel(
    const float* __restrict__ emb,
    const float* __restrict__ W1, const float* __restrict__ b1,
    const float* __restrict__ W2, const float* __restrict__ b2,
    const float* __restrict__ W3, const float* __restrict__ b3,
    const float* __restrict__ A1, const float* __restrict__ a1,
    const float* __restrict__ A2, const float* __restrict__ a2,
    const float* __restrict__ C1)
{
#if __CUDA_ARCH__ >= 900
    cudaTriggerProgrammaticLaunchCompletion();
#endif
    const int v = blockIdx.x;
    const int t = threadIdx.x;  // 256 threads
    __shared__ float e[Dq];
    __shared__ float h1[64];
    __shared__ float g1[64];
    __shared__ float h2[32];
    __shared__ float att_s[Dq];

    if (t < Dq) e[t] = emb[v * Dq + t];
    __syncthreads();

    // layer 1: both W1 and A1. 256 threads = 2 mats x 64 neurons x 2 halves.
    {
        const int mat = t >> 7;          // 0 -> W1 path, 1 -> A1 path
        const int n   = (t & 127) >> 1;  // neuron 0..63
        const int p   = t & 1;           // half 0..1
        const float* M = mat ? A1 : W1;
        float s = 0.f;
        const int base = p * 64;
        #pragma unroll
        for (int i = 0; i < 64; i++)
            s += e[base + i] * M[(base + i) * 64 + n];
        s += __shfl_xor_sync(0xffffffff, s, 1);
        if (p == 0) {
            if (mat == 0) h1[n] = fmaxf(s + b1[n], 0.f);
            else          g1[n] = fmaxf(s + a1[n], 0.f);
        }
    }
    __syncthreads();

    // layer 2 (W2): 32 neurons x 4 threads (uses threads 0..127)
    if (t < 128) {
        const int n = t >> 2, p = t & 3;
        float s = 0.f;
        const int base = p * 16;
        #pragma unroll
        for (int i = 0; i < 16; i++)
            s += h1[base + i] * W2[(base + i) * 32 + n];
        s += __shfl_xor_sync(0xffffffff, s, 1);
        s += __shfl_xor_sync(0xffffffff, s, 2);
        if (p == 0) h2[n] = fmaxf(s + b2[n], 0.f);
    }
    // A2: 128 outputs x 2 threads (all 256 threads) -> att_s (smem only)
    {
        const int j = t >> 1, p = t & 1;
        float s = 0.f;
        const int base = p * 32;
        #pragma unroll
        for (int i = 0; i < 32; i++)
            s += g1[base + i] * A2[(base + i) * Dq + j];
        s += __shfl_xor_sync(0xffffffff, s, 1);
        if (p == 0) att_s[j] = s + a2[j];
    }
    __syncthreads();

    // layer 3: warp 0 reduces 32 values -> sigmoid score
    if (t < 32) {
        float z = h2[t] * W3[t];
        #pragma unroll
        for (int d = 16; d >= 1; d >>= 1) z += __shfl_xor_sync(0xffffffff, z, d);
        if (t == 0) g_score[v] = 1.f / (1.f + expf(-(z + b3[0])));
    }

    // folded classifier table: attC1[v][n] = att_v @ C1[:,n]
    // 64 neurons x 4 threads (32 inputs each)
    {
        const int n = t >> 2, p = t & 3;
        float s = 0.f;
        const int base = p * 32;
        #pragma unroll
        for (int i = 0; i < 32; i++)
            s += att_s[base + i] * C1[(base + i) * 64 + n];
        s += __shfl_xor_sync(0xffffffff, s, 1);
        s += __shfl_xor_sync(0xffffffff, s, 2);
        if (p == 0) g_attC1[v * 64 + n] = s;
    }
}

// ---------------------------------------------------------------------------
// Kernel 2: one CTA per batch row. 256 threads, 16 contiguous tokens/thread.
// SHFL-routed dynamic indexing, packed-u64 ranks, folded single-warp
// classifier epilogue. Two block barriers total.
// ---------------------------------------------------------------------------
__global__ __launch_bounds__(256, 4) void main_kernel(
    const int* __restrict__ x,
    const float* __restrict__ c1,
    const float* __restrict__ C2, const float* __restrict__ c2,
    float* __restrict__ out)
{
    const int b = blockIdx.x;
    const int t = threadIdx.x;  // 256 threads
    const int w = t >> 5, l = t & 31;

    __shared__ unsigned long long wtot[8];  // per-warp packed totals
    __shared__ float sh_idx[Kq];

    // ---------- score-independent front half (overlaps precompute) ----------
    const int4* xb = (const int4*)(x + (size_t)b * Sq);

    int4 P[4];
    unsigned long long hist = 0ull;
    #pragma unroll
    for (int i = 0; i < 4; i++) {
        int4 p = xb[t * 4 + i];
        P[i] = p;
        hist += 1ull << (p.x * 10);
        hist += 1ull << (p.y * 10);
        hist += 1ull << (p.z * 10);
        hist += 1ull << (p.w * 10);
    }

    // warp-level packed inclusive scan (10-bit fields)
    unsigned long long run = hist;
    #pragma unroll
    for (int d = 1; d < 32; d <<= 1) {
        unsigned long long o = __shfl_up_sync(0xffffffff, run, d);
        if (l >= d) run += o;
    }
    const unsigned long long excl = run - hist;
    if (l == 31) wtot[w] = run;
    __syncthreads();  // barrier 1

    // cross-warp: packed exclusive base (pcnt) + per-value block totals
    unsigned long long pcnt;
    int tot[Vq];
    {
        unsigned long long pre = 0ull, all = 0ull;
        #pragma unroll
        for (int ww = 0; ww < 8; ww++) {
            unsigned long long tw = wtot[ww];
            if (ww < w) pre += tw;
            all += tw;
        }
        pcnt = pre + excl;   // packed per-value rank counters for this thread
        #pragma unroll
        for (int v = 0; v < Vq; v++)
            tot[v] = (int)((all >> (v * 10)) & 0x3FF);
    }

    // ---------- wait for precompute results ----------
#if __CUDA_ARCH__ >= 900
    cudaGridDependencySynchronize();
#endif

    float sc[Vq];
    #pragma unroll
    for (int v = 0; v < Vq; v++) sc[v] = g_score[v];

    // lane-resident score for dynamic gather via shfl
    const int v_me = (l < Vq) ? l : (Vq - 1);
    const float scf = sc[v_me];

    // per-lane rank offset: offraw_l = sum of tot[u] for u preceding v_me
    // (u precedes v  <=>  s_u > s_v || (s_u == s_v && u < v))
    int offraw_lane = 0;
    #pragma unroll
    for (int u = 0; u < Vq; u++) {
        bool prec = (u != v_me) &&
                    ((sc[u] > sc[v_me]) || (sc[u] == sc[v_me] && u < v_me));
        offraw_lane += prec ? tot[u] : 0;
    }

    // ---------- fused fs-store + compaction pass ----------
    float* fs = out + Bq + (size_t)Bq * Kq + (size_t)b * Sq;
    #pragma unroll
    for (int i = 0; i < 4; i++) {
        const int* pv = (const int*)&P[i];
        float4 f;
        float* fp = (float*)&f;
        #pragma unroll
        for (int j = 0; j < 4; j++) {
            const int vv = pv[j];
            fp[j] = __shfl_sync(0xffffffff, scf, vv);
            const int ofr = __shfl_sync(0xffffffff, offraw_lane, vv);
            const int sh = vv * 10;
            const int rank = (int)((pcnt >> sh) & 0x3FF);
            pcnt += 1ull << sh;
            const int pos = ofr + rank;
            if (pos < Kq) sh_idx[pos] = (float)(t * 16 + i * 4 + j);
        }
        ((float4*)fs)[t * 4 + i] = f;
    }
    __syncthreads();  // barrier 2

    float* oidx = out + Bq + (size_t)b * Kq;
    oidx[t] = sh_idx[t];
    if (t < Kq - 256) oidx[t + 256] = sh_idx[t + 256];

    // ---------- folded classifier epilogue (warp 0 only) ----------
    // z1[n] = (1/K) * sum_v take_v * attC1[v][n] + c1[n];  h = relu(z1)
    // pred  = sigmoid(sum_n h[n]*C2[n] + c2)
    if (w == 0) {
        float takef[Vq];
        #pragma unroll
        for (int v = 0; v < Vq; v++) {
            const int ofr = __shfl_sync(0xffffffff, offraw_lane, v);
            takef[v] = (float)max(0, min(Kq - ofr, tot[v]));
        }
        const float invK = 1.f / (float)Kq;
        float zacc = 0.f;
        #pragma unroll
        for (int hh = 0; hh < 2; hh++) {
            const int n = l + hh * 32;
            float s = 0.f;
            #pragma unroll
            for (int v = 0; v < Vq; v++)
                s += takef[v] * g_attC1[v * 64 + n];
            const float h = fmaxf(fmaf(s, invK, c1[n]), 0.f);
            zacc += h * C2[n];
        }
        #pragma unroll
        for (int d = 16; d >= 1; d >>= 1)
            zacc += __shfl_xor_sync(0xffffffff, zacc, d);
        if (l == 0) out[b] = 1.f / (1.f + expf(-(zacc + c2[0])));
    }
}

extern "C" void kernel_launch(void* const* d_in, const int* in_sizes, int n_in,
                              void* d_out, int out_size) {
    const int*   x   = (const int*)d_in[0];
    const float* emb = (const float*)d_in[1];
    const float* W1  = (const float*)d_in[2];
    const float* b1  = (const float*)d_in[3];
    const float* W2  = (const float*)d_in[4];
    const float* b2  = (const float*)d_in[5];
    const float* W3  = (const float*)d_in[6];
    const float* b3  = (const float*)d_in[7];
    const float* A1  = (const float*)d_in[8];
    const float* a1  = (const float*)d_in[9];
    const float* A2  = (const float*)d_in[10];
    const float* a2  = (const float*)d_in[11];
    const float* C1  = (const float*)d_in[12];
    const float* c1  = (const float*)d_in[13];
    const float* C2  = (const float*)d_in[14];
    const float* c2  = (const float*)d_in[15];
    float* out = (float*)d_out;

    precompute_kernel<<<Vq, 256>>>(emb, W1, b1, W2, b2, W3, b3,
                                   A1, a1, A2, a2, C1);

    // PDL: main_kernel may begin before precompute finishes; it gates on
    // cudaGridDependencySynchronize() before consuming g_score/g_attC1.
    cudaLaunchConfig_t cfg = {};
    cfg.gridDim  = dim3(Bq, 1, 1);
    cfg.blockDim = dim3(256, 1, 1);
    cfg.dynamicSmemBytes = 0;
    cfg.stream = 0;
    cudaLaunchAttribute attr[1];
    attr[0].id = cudaLaunchAttributeProgrammaticStreamSerialization;
    attr[0].val.programmaticStreamSerializationAllowed = 1;
    cfg.attrs = attr;
    cfg.numAttrs = 1;
    cudaLaunchKernelEx(&cfg, main_kernel, x, c1, C2, c2, out);
}